// round 7
// baseline (speedup 1.0000x reference)
#include <cuda_runtime.h>
#include <cuda_fp16.h>
#include <cstdint>

// BarycentricInterpolator: out[b, m] = sum_k f[b, tri[m,k]] * w[m,k]
// B=128, N=10000, M=500000.
//
// R7: same theory as R5/R6 (never measured: two infra failures) with an
// equivalent, simpler pipeline structure:
//  * register double-buffered record loads hide ~250cyc L2 latency behind
//    LDS/HFMA2/STG of the current iteration (predicated prefetch)
//  * 512 thr x 2 blocks/SM (64-reg budget), fp16 smem tiles, half2 math

#define BB 4
#define MAX_M 600000

__device__ __align__(16) uint4 g_recs[MAX_M];
// record: x = i0 | i1<<16 ; y = i2 | h(w2)<<16 ; z = h2(w0,w0) ; w = h2(w1,w1)

__global__ void pack_kernel(const int* __restrict__ tri,
                            const float* __restrict__ w,
                            int M) {
    int m = blockIdx.x * blockDim.x + threadIdx.x;
    if (m >= M) return;
    unsigned i0 = (unsigned)tri[3 * m + 0];
    unsigned i1 = (unsigned)tri[3 * m + 1];
    unsigned i2 = (unsigned)tri[3 * m + 2];
    float w0 = w[3 * m + 0];
    float w1 = w[3 * m + 1];
    float w2 = 1.0f - w0 - w1;
    unsigned h0 = (unsigned)__half_as_ushort(__float2half_rn(w0));
    unsigned h1 = (unsigned)__half_as_ushort(__float2half_rn(w1));
    unsigned h2 = (unsigned)__half_as_ushort(__float2half_rn(w2));
    uint4 r;
    r.x = (i0 & 0xFFFFu) | (i1 << 16);
    r.y = (i2 & 0xFFFFu) | (h2 << 16);
    r.z = h0 | (h0 << 16);
    r.w = h1 | (h1 << 16);
    g_recs[m] = r;
}

__device__ __forceinline__ __half2 u2h(unsigned u) {
    return *reinterpret_cast<__half2*>(&u);
}

__global__ void __launch_bounds__(512, 2)
interp_kernel(const float* __restrict__ f,
              float* __restrict__ out,
              int Bv, int Nv, int Mv) {
    extern __shared__ __half fsh[];                 // BB * Nv halves, fsh[i*4 + bl]
    const uint2* __restrict__ fs2 = reinterpret_cast<const uint2*>(fsh);

    const int NB = Bv / BB;                         // 32 b-groups
    const long long J = (long long)NB * (long long)Mv;

    long long j0 = (long long)blockIdx.x * J / gridDim.x;
    long long j1 = (long long)(blockIdx.x + 1) * J / gridDim.x;
    j0 &= ~3LL;                                     // STG.128 alignment (Mv % 4 == 0)
    if (blockIdx.x + 1 != gridDim.x) j1 &= ~3LL;

    long long j = j0;
    while (j < j1) {
        const int gb = (int)(j / Mv);
        const long long seg_end = min(j1, (long long)(gb + 1) * (long long)Mv);

        // ---- stage BB rows of f into smem as fp16, interleaved [i*4 + bl] ----
        {
            const float* frow = f + (long long)gb * BB * Nv;
            const int tot = BB * Nv;
            for (int t = threadIdx.x; t < tot; t += blockDim.x) {
                int bl = t / Nv;
                int i  = t - bl * Nv;
                fsh[i * BB + bl] = __float2half_rn(frow[(long long)bl * Nv + i]);
            }
        }
        __syncthreads();

        const int m_lo = (int)(j - (long long)gb * Mv);
        const int m_hi = (int)(seg_end - (long long)gb * Mv);
        float* __restrict__ outb = out + (long long)gb * BB * Mv;

        const int stride = 4 * (int)blockDim.x;
        int m = m_lo + 4 * (int)threadIdx.x;

        if (m + 3 < m_hi) {
            // prime the pipeline
            uint4 rc0 = __ldcg(&g_recs[m]);
            uint4 rc1 = __ldcg(&g_recs[m + 1]);
            uint4 rc2 = __ldcg(&g_recs[m + 2]);
            uint4 rc3 = __ldcg(&g_recs[m + 3]);

            for (;;) {
                const int m_next = m + stride;
                const bool more = (m_next + 3 < m_hi);

                // predicated prefetch of next iteration's records
                uint4 rn0, rn1, rn2, rn3;
                if (more) {
                    rn0 = __ldcg(&g_recs[m_next]);
                    rn1 = __ldcg(&g_recs[m_next + 1]);
                    rn2 = __ldcg(&g_recs[m_next + 2]);
                    rn3 = __ldcg(&g_recs[m_next + 3]);
                }

                // ---- compute + store current 4 m's x 4 b's ----
                {
                    uint4 r[4] = {rc0, rc1, rc2, rc3};
                    __half2 accA[4], accB[4];
                    #pragma unroll
                    for (int k = 0; k < 4; k++) {
                        const int i0 = r[k].x & 0xFFFFu;
                        const int i1 = r[k].x >> 16;
                        const int i2 = r[k].y & 0xFFFFu;
                        const __half2 w0 = u2h(r[k].z);
                        const __half2 w1 = u2h(r[k].w);
                        const __half2 w2 =
                            __half2half2(__ushort_as_half((unsigned short)(r[k].y >> 16)));
                        uint2 va = fs2[i0];
                        uint2 vb = fs2[i1];
                        uint2 vc = fs2[i2];
                        accA[k] = __hfma2(w0, u2h(va.x),
                                  __hfma2(w1, u2h(vb.x), __hmul2(w2, u2h(vc.x))));
                        accB[k] = __hfma2(w0, u2h(va.y),
                                  __hfma2(w1, u2h(vb.y), __hmul2(w2, u2h(vc.y))));
                    }
                    float* o = outb + m;
                    __stcs(reinterpret_cast<float4*>(o),
                           make_float4(__low2float(accA[0]),  __low2float(accA[1]),
                                       __low2float(accA[2]),  __low2float(accA[3])));
                    __stcs(reinterpret_cast<float4*>(o + Mv),
                           make_float4(__high2float(accA[0]), __high2float(accA[1]),
                                       __high2float(accA[2]), __high2float(accA[3])));
                    __stcs(reinterpret_cast<float4*>(o + 2 * Mv),
                           make_float4(__low2float(accB[0]),  __low2float(accB[1]),
                                       __low2float(accB[2]),  __low2float(accB[3])));
                    __stcs(reinterpret_cast<float4*>(o + 3 * Mv),
                           make_float4(__high2float(accB[0]), __high2float(accB[1]),
                                       __high2float(accB[2]), __high2float(accB[3])));
                }

                if (!more) break;
                rc0 = rn0; rc1 = rn1; rc2 = rn2; rc3 = rn3;
                m = m_next;
            }
            m += stride;
        }
        // robustness tail (ranges are 4-aligned in practice; normally empty)
        for (; m < m_hi; m++) {
            uint4 rr = __ldcg(&g_recs[m]);
            const int i0 = rr.x & 0xFFFFu;
            const int i1 = rr.x >> 16;
            const int i2 = rr.y & 0xFFFFu;
            const __half2 w0 = u2h(rr.z);
            const __half2 w1 = u2h(rr.w);
            const __half2 w2 = __half2half2(__ushort_as_half((unsigned short)(rr.y >> 16)));
            uint2 va = fs2[i0];
            uint2 vb = fs2[i1];
            uint2 vc = fs2[i2];
            __half2 sA = __hfma2(w0, u2h(va.x), __hfma2(w1, u2h(vb.x), __hmul2(w2, u2h(vc.x))));
            __half2 sB = __hfma2(w0, u2h(va.y), __hfma2(w1, u2h(vb.y), __hmul2(w2, u2h(vc.y))));
            float* o = outb + m;
            __stcs(o,          __low2float(sA));
            __stcs(o + Mv,     __high2float(sA));
            __stcs(o + 2 * Mv, __low2float(sB));
            __stcs(o + 3 * Mv, __high2float(sB));
        }
        __syncthreads();
        j = seg_end;
    }
}

// Exact-fp32 fallback for shapes the fast path can't handle.
__global__ void naive_kernel(const float* __restrict__ f,
                             const int* __restrict__ tri,
                             const float* __restrict__ w,
                             float* __restrict__ out,
                             int B, int N, int M) {
    int m = blockIdx.x * blockDim.x + threadIdx.x;
    if (m >= M) return;
    int i0 = tri[3 * m], i1 = tri[3 * m + 1], i2 = tri[3 * m + 2];
    float w0 = w[3 * m], w1 = w[3 * m + 1], w2 = w[3 * m + 2];
    for (int b = 0; b < B; b++) {
        out[(long long)b * M + m] =
            w0 * f[(long long)b * N + i0] +
            w1 * f[(long long)b * N + i1] +
            w2 * f[(long long)b * N + i2];
    }
}

extern "C" void kernel_launch(void* const* d_in, const int* in_sizes, int n_in,
                              void* d_out, int out_size) {
    const float* f   = (const float*)d_in[0];
    const int*   tri = (const int*)d_in[1];
    const float* w   = (const float*)d_in[2];
    float* out = (float*)d_out;

    const int M = in_sizes[1] / 3;
    const int B = out_size / M;
    const int N = in_sizes[0] / B;

    const bool fast = (B % BB == 0) && (N <= 14000) &&
                      (M <= MAX_M) && (M % 4 == 0);

    if (!fast) {
        naive_kernel<<<(M + 255) / 256, 256>>>(f, tri, w, out, B, N, M);
        return;
    }

    pack_kernel<<<(M + 255) / 256, 256>>>(tri, w, M);

    int sms = 148;
    cudaDeviceGetAttribute(&sms, cudaDevAttrMultiProcessorCount, 0);

    const int smem_bytes = BB * N * (int)sizeof(__half);   // 80 KB at N=10000
    cudaFuncSetAttribute(interp_kernel,
                         cudaFuncAttributeMaxDynamicSharedMemorySize, smem_bytes);

    const int grid = 2 * sms;   // 2 blocks resident per SM, single wave
    interp_kernel<<<grid, 512, smem_bytes>>>(f, out, B, N, M);
}

// round 8
// speedup vs baseline: 1.3001x; 1.3001x over previous
#include <cuda_runtime.h>
#include <cuda_fp16.h>
#include <cstdint>

// BarycentricInterpolator: out[b, m] = sum_k f[b, tri[m,k]] * w[m,k]
// B=128, N=10000, M=500000.
//
// R8 = R4 (best measured: 124.9us, 768thr x 2 blocks/SM, BB=4 fp16 tile,
// half2 math, no prefetch) with ONE change: the smem fill is now
// division-free and vectorized (4x LDG.128 + 8x F2FP + 2x STS.128 per
// 16 elements instead of ~14 instrs/element with a runtime int division).

#define BB 4
#define MAX_M 600000

__device__ __align__(16) uint4 g_recs[MAX_M];
// record: x = i0 | i1<<16 ; y = i2 | h(w2)<<16 ; z = h2(w0,w0) ; w = h2(w1,w1)

__global__ void pack_kernel(const int* __restrict__ tri,
                            const float* __restrict__ w,
                            int M) {
    int m = blockIdx.x * blockDim.x + threadIdx.x;
    if (m >= M) return;
    unsigned i0 = (unsigned)tri[3 * m + 0];
    unsigned i1 = (unsigned)tri[3 * m + 1];
    unsigned i2 = (unsigned)tri[3 * m + 2];
    float w0 = w[3 * m + 0];
    float w1 = w[3 * m + 1];
    float w2 = 1.0f - w0 - w1;
    unsigned h0 = (unsigned)__half_as_ushort(__float2half_rn(w0));
    unsigned h1 = (unsigned)__half_as_ushort(__float2half_rn(w1));
    unsigned h2 = (unsigned)__half_as_ushort(__float2half_rn(w2));
    uint4 r;
    r.x = (i0 & 0xFFFFu) | (i1 << 16);
    r.y = (i2 & 0xFFFFu) | (h2 << 16);
    r.z = h0 | (h0 << 16);
    r.w = h1 | (h1 << 16);
    g_recs[m] = r;
}

__device__ __forceinline__ __half2 u2h(unsigned u) {
    return *reinterpret_cast<__half2*>(&u);
}

__device__ __forceinline__ unsigned packh2(float a, float b) {
    __half2 h = __floats2half2_rn(a, b);   // .x = a (low), .y = b (high)
    return *reinterpret_cast<unsigned*>(&h);
}

__global__ void __launch_bounds__(768, 2)
interp_kernel(const float* __restrict__ f,
              float* __restrict__ out,
              int Bv, int Nv, int Mv) {
    extern __shared__ __half fsh[];                 // BB * Nv halves, fsh[i*4 + bl]
    const uint2* __restrict__ fs2 = reinterpret_cast<const uint2*>(fsh);

    const int NB = Bv / BB;                         // 32 b-groups
    const long long J = (long long)NB * (long long)Mv;

    long long j0 = (long long)blockIdx.x * J / gridDim.x;
    long long j1 = (long long)(blockIdx.x + 1) * J / gridDim.x;
    j0 &= ~3LL;                                     // STG.128 alignment (Mv % 4 == 0)
    if (blockIdx.x + 1 != gridDim.x) j1 &= ~3LL;

    long long j = j0;
    while (j < j1) {
        const int gb = (int)(j / Mv);
        const long long seg_end = min(j1, (long long)(gb + 1) * (long long)Mv);

        // ---- stage BB rows of f into smem as fp16, interleaved [i*4 + bl] ----
        {
            const float* frow = f + (long long)gb * BB * Nv;
            if ((Nv & 3) == 0) {
                // division-free vectorized transpose-fill:
                // per q: 4 consecutive columns (i = 4q..4q+3) of all 4 rows
                const float4* r0 = reinterpret_cast<const float4*>(frow);
                const float4* r1 = reinterpret_cast<const float4*>(frow + Nv);
                const float4* r2 = reinterpret_cast<const float4*>(frow + 2 * Nv);
                const float4* r3 = reinterpret_cast<const float4*>(frow + 3 * Nv);
                uint4* dst = reinterpret_cast<uint4*>(fsh);   // 2 columns per uint4
                const int nq = Nv >> 2;
                for (int q = threadIdx.x; q < nq; q += blockDim.x) {
                    float4 a = r0[q], b = r1[q], c = r2[q], d = r3[q];
                    uint4 u0, u1;
                    u0.x = packh2(a.x, b.x); u0.y = packh2(c.x, d.x);   // i = 4q
                    u0.z = packh2(a.y, b.y); u0.w = packh2(c.y, d.y);   // i = 4q+1
                    u1.x = packh2(a.z, b.z); u1.y = packh2(c.z, d.z);   // i = 4q+2
                    u1.z = packh2(a.w, b.w); u1.w = packh2(c.w, d.w);   // i = 4q+3
                    dst[2 * q]     = u0;
                    dst[2 * q + 1] = u1;
                }
            } else {
                const int tot = BB * Nv;
                for (int t = threadIdx.x; t < tot; t += blockDim.x) {
                    int bl = t / Nv;
                    int i  = t - bl * Nv;
                    fsh[i * BB + bl] = __float2half_rn(frow[(long long)bl * Nv + i]);
                }
            }
        }
        __syncthreads();

        const int m_lo = (int)(j - (long long)gb * Mv);
        const int m_hi = (int)(seg_end - (long long)gb * Mv);
        float* __restrict__ outb = out + (long long)gb * BB * Mv;

        int m = m_lo + 4 * (int)threadIdx.x;
        const int stride = 4 * (int)blockDim.x;
        for (; m + 3 < m_hi; m += stride) {
            uint4 r[4];
            r[0] = __ldcg(&g_recs[m]);
            r[1] = __ldcg(&g_recs[m + 1]);
            r[2] = __ldcg(&g_recs[m + 2]);
            r[3] = __ldcg(&g_recs[m + 3]);

            __half2 accA[4];   // b-pair {0,1} for m..m+3
            __half2 accB[4];   // b-pair {2,3}

            #pragma unroll
            for (int k = 0; k < 4; k++) {
                const int i0 = r[k].x & 0xFFFFu;
                const int i1 = r[k].x >> 16;
                const int i2 = r[k].y & 0xFFFFu;
                const __half2 w0 = u2h(r[k].z);
                const __half2 w1 = u2h(r[k].w);
                const __half2 w2 = __half2half2(__ushort_as_half((unsigned short)(r[k].y >> 16)));

                uint2 va = fs2[i0];
                uint2 vb = fs2[i1];
                uint2 vc = fs2[i2];

                accA[k] = __hfma2(w0, u2h(va.x),
                          __hfma2(w1, u2h(vb.x), __hmul2(w2, u2h(vc.x))));
                accB[k] = __hfma2(w0, u2h(va.y),
                          __hfma2(w1, u2h(vb.y), __hmul2(w2, u2h(vc.y))));
            }

            float* o = outb + m;
            __stcs(reinterpret_cast<float4*>(o),
                   make_float4(__low2float(accA[0]),  __low2float(accA[1]),
                               __low2float(accA[2]),  __low2float(accA[3])));
            __stcs(reinterpret_cast<float4*>(o + Mv),
                   make_float4(__high2float(accA[0]), __high2float(accA[1]),
                               __high2float(accA[2]), __high2float(accA[3])));
            __stcs(reinterpret_cast<float4*>(o + 2 * Mv),
                   make_float4(__low2float(accB[0]),  __low2float(accB[1]),
                               __low2float(accB[2]),  __low2float(accB[3])));
            __stcs(reinterpret_cast<float4*>(o + 3 * Mv),
                   make_float4(__high2float(accB[0]), __high2float(accB[1]),
                               __high2float(accB[2]), __high2float(accB[3])));
        }
        // robustness tail (ranges are 4-aligned in practice)
        for (; m < m_hi; m++) {
            uint4 rr = __ldcg(&g_recs[m]);
            const int i0 = rr.x & 0xFFFFu;
            const int i1 = rr.x >> 16;
            const int i2 = rr.y & 0xFFFFu;
            const __half2 w0 = u2h(rr.z);
            const __half2 w1 = u2h(rr.w);
            const __half2 w2 = __half2half2(__ushort_as_half((unsigned short)(rr.y >> 16)));
            uint2 va = fs2[i0];
            uint2 vb = fs2[i1];
            uint2 vc = fs2[i2];
            __half2 sA = __hfma2(w0, u2h(va.x), __hfma2(w1, u2h(vb.x), __hmul2(w2, u2h(vc.x))));
            __half2 sB = __hfma2(w0, u2h(va.y), __hfma2(w1, u2h(vb.y), __hmul2(w2, u2h(vc.y))));
            float* o = outb + m;
            __stcs(o,          __low2float(sA));
            __stcs(o + Mv,     __high2float(sA));
            __stcs(o + 2 * Mv, __low2float(sB));
            __stcs(o + 3 * Mv, __high2float(sB));
        }
        __syncthreads();
        j = seg_end;
    }
}

// Exact-fp32 fallback for shapes the fast path can't handle.
__global__ void naive_kernel(const float* __restrict__ f,
                             const int* __restrict__ tri,
                             const float* __restrict__ w,
                             float* __restrict__ out,
                             int B, int N, int M) {
    int m = blockIdx.x * blockDim.x + threadIdx.x;
    if (m >= M) return;
    int i0 = tri[3 * m], i1 = tri[3 * m + 1], i2 = tri[3 * m + 2];
    float w0 = w[3 * m], w1 = w[3 * m + 1], w2 = w[3 * m + 2];
    for (int b = 0; b < B; b++) {
        out[(long long)b * M + m] =
            w0 * f[(long long)b * N + i0] +
            w1 * f[(long long)b * N + i1] +
            w2 * f[(long long)b * N + i2];
    }
}

extern "C" void kernel_launch(void* const* d_in, const int* in_sizes, int n_in,
                              void* d_out, int out_size) {
    const float* f   = (const float*)d_in[0];
    const int*   tri = (const int*)d_in[1];
    const float* w   = (const float*)d_in[2];
    float* out = (float*)d_out;

    const int M = in_sizes[1] / 3;
    const int B = out_size / M;
    const int N = in_sizes[0] / B;

    const bool fast = (B % BB == 0) && (N <= 14000) &&
                      (M <= MAX_M) && (M % 4 == 0);

    if (!fast) {
        naive_kernel<<<(M + 255) / 256, 256>>>(f, tri, w, out, B, N, M);
        return;
    }

    pack_kernel<<<(M + 255) / 256, 256>>>(tri, w, M);

    int sms = 148;
    cudaDeviceGetAttribute(&sms, cudaDevAttrMultiProcessorCount, 0);

    const int smem_bytes = BB * N * (int)sizeof(__half);   // 80 KB at N=10000
    cudaFuncSetAttribute(interp_kernel,
                         cudaFuncAttributeMaxDynamicSharedMemorySize, smem_bytes);

    const int grid = 2 * sms;   // 2 blocks resident per SM, single wave
    interp_kernel<<<grid, 768, smem_bytes>>>(f, out, B, N, M);
}